// round 9
// baseline (speedup 1.0000x reference)
#include <cuda_runtime.h>

// FWHT-128 over the last dim of three (4,32,4096,128) fp32 tensors.
// 256-bit (v8.f32) global loads/stores, 2 rows per thread -> 4 front-batched
// LDG.256 per thread (4KB independent reads per warp in flight).
// Mapping: 8 lanes per row (j = lane&7); thread handles rows
//   rowA = warp*8 + (lane>>3) and rowB = rowA + 4.
// Per row: two contiguous 8-float chunks at elements {8j..8j+7}, {64+8j..64+8j+7}.
//   In-register stages: h=1,2,4 (inside chunk), h=64 (between chunks).
//   Shuffle stages:     h=8,16,32 -> __shfl_xor masks 1,2,4 (within 8-lane group).

__device__ __forceinline__ void ldg256_cs(const float* p, float* r) {
    asm volatile("ld.global.cs.v8.f32 {%0,%1,%2,%3,%4,%5,%6,%7}, [%8];"
        : "=f"(r[0]), "=f"(r[1]), "=f"(r[2]), "=f"(r[3]),
          "=f"(r[4]), "=f"(r[5]), "=f"(r[6]), "=f"(r[7])
        : "l"(p));
}

__device__ __forceinline__ void stg256_cs(float* p, const float* r) {
    asm volatile("st.global.cs.v8.f32 [%0], {%1,%2,%3,%4,%5,%6,%7,%8};"
        :: "l"(p),
           "f"(r[0]), "f"(r[1]), "f"(r[2]), "f"(r[3]),
           "f"(r[4]), "f"(r[5]), "f"(r[6]), "f"(r[7])
        : "memory");
}

__global__ __launch_bounds__(256) void fwht128_kernel(
    const float* __restrict__ q,
    const float* __restrict__ k,
    const float* __restrict__ v,
    float* __restrict__ out,
    int rowsPerArr)
{
    const int lane = threadIdx.x & 31;
    const int warpGlobal = (int)((blockIdx.x * blockDim.x + threadIdx.x) >> 5);
    const int rowA = warpGlobal * 8 + (lane >> 3);
    const int rowB = rowA + 4;
    const int j = lane & 7;

    const float* __restrict__ src = (blockIdx.y == 0) ? q : (blockIdx.y == 1) ? k : v;

    const size_t baseA = (size_t)rowA * 128 + j * 8;
    const size_t baseB = (size_t)rowB * 128 + j * 8;

    // 4 front-batched 256-bit loads (2KB/thread in flight), streaming hint.
    float a0[8], a1[8], b0[8], b1[8];
    ldg256_cs(src + baseA,      a0);
    ldg256_cs(src + baseA + 64, a1);
    ldg256_cs(src + baseB,      b0);
    ldg256_cs(src + baseB + 64, b1);

    // ---- In-chunk stages h=1,2,4 ----
    #define CHUNK_H1(c) { float t; \
        t=c[0]; c[0]=t+c[1]; c[1]=t-c[1]; \
        t=c[2]; c[2]=t+c[3]; c[3]=t-c[3]; \
        t=c[4]; c[4]=t+c[5]; c[5]=t-c[5]; \
        t=c[6]; c[6]=t+c[7]; c[7]=t-c[7]; }
    #define CHUNK_H2(c) { float t; \
        t=c[0]; c[0]=t+c[2]; c[2]=t-c[2]; \
        t=c[1]; c[1]=t+c[3]; c[3]=t-c[3]; \
        t=c[4]; c[4]=t+c[6]; c[6]=t-c[6]; \
        t=c[5]; c[5]=t+c[7]; c[7]=t-c[7]; }
    #define CHUNK_H4(c) { float t; \
        t=c[0]; c[0]=t+c[4]; c[4]=t-c[4]; \
        t=c[1]; c[1]=t+c[5]; c[5]=t-c[5]; \
        t=c[2]; c[2]=t+c[6]; c[6]=t-c[6]; \
        t=c[3]; c[3]=t+c[7]; c[7]=t-c[7]; }
    CHUNK_H1(a0) CHUNK_H1(a1) CHUNK_H1(b0) CHUNK_H1(b1)
    CHUNK_H2(a0) CHUNK_H2(a1) CHUNK_H2(b0) CHUNK_H2(b1)
    CHUNK_H4(a0) CHUNK_H4(a1) CHUNK_H4(b0) CHUNK_H4(b1)

    // ---- Stages h=8,16,32: element bits 3,4,5 live in j -> masks 1,2,4 ----
    #pragma unroll
    for (int m = 1; m <= 4; m <<= 1) {
        const float sgn = (j & m) ? -1.0f : 1.0f;
        #define SHFL8(c) { \
            _Pragma("unroll") \
            for (int i = 0; i < 8; i++) { \
                float p = __shfl_xor_sync(0xffffffffu, c[i], m); \
                c[i] = fmaf(c[i], sgn, p); } }
        SHFL8(a0) SHFL8(a1) SHFL8(b0) SHFL8(b1)
        #undef SHFL8
    }

    // ---- Stage h=64: between chunks; fold in final 1/sqrt(128) scale ----
    const float s = 0.08838834764831845f;
    #pragma unroll
    for (int i = 0; i < 8; i++) {
        float t = a0[i];
        a0[i] = (t + a1[i]) * s;
        a1[i] = (t - a1[i]) * s;
        t = b0[i];
        b0[i] = (t + b1[i]) * s;
        b1[i] = (t - b1[i]) * s;
    }

    float* __restrict__ dst = out + (size_t)blockIdx.y * rowsPerArr * 128;
    stg256_cs(dst + baseA,      a0);
    stg256_cs(dst + baseA + 64, a1);
    stg256_cs(dst + baseB,      b0);
    stg256_cs(dst + baseB + 64, b1);
}

extern "C" void kernel_launch(void* const* d_in, const int* in_sizes, int n_in,
                              void* d_out, int out_size)
{
    const float* q = (const float*)d_in[0];
    const float* k = (const float*)d_in[1];
    const float* v = (const float*)d_in[2];
    float* out = (float*)d_out;

    const int rowsPerArr = in_sizes[0] / 128;   // 524288 (multiple of 64)
    const int rowsPerBlock = (256 / 32) * 8;    // 8 warps * 8 rows = 64
    const int blocksX = rowsPerArr / rowsPerBlock;

    dim3 grid(blocksX, 3, 1);
    fwht128_kernel<<<grid, 256>>>(q, k, v, out, rowsPerArr);
}

// round 10
// speedup vs baseline: 1.0088x; 1.0088x over previous
#include <cuda_runtime.h>

// FWHT-128 over the last dim of three (4,32,4096,128) fp32 tensors.
// Best-measured config (R8): 256-bit (v8.f32) global loads/stores, 1 row per
// thread slice, 8 lanes per row (j = lane&7), 4 rows per warp, regs=32,
// occ ~76%, DRAM 87.2%.
// Each thread owns two contiguous 8-float chunks of its row:
// elements {8j..8j+7} and {64+8j..64+8j+7} (32-byte aligned).
//   In-register stages: h=1,2,4 (inside each chunk), h=64 (between chunks).
//   Shuffle stages:     h=8,16,32 -> __shfl_xor masks 1,2,4 (within 8-lane group).
// Loads are non-volatile asm so ptxas can front-batch them freely.

__device__ __forceinline__ void ldg256_cs(const float* p, float* r) {
    asm("ld.global.cs.v8.f32 {%0,%1,%2,%3,%4,%5,%6,%7}, [%8];"
        : "=f"(r[0]), "=f"(r[1]), "=f"(r[2]), "=f"(r[3]),
          "=f"(r[4]), "=f"(r[5]), "=f"(r[6]), "=f"(r[7])
        : "l"(p));
}

__device__ __forceinline__ void stg256_cs(float* p, const float* r) {
    asm volatile("st.global.cs.v8.f32 [%0], {%1,%2,%3,%4,%5,%6,%7,%8};"
        :: "l"(p),
           "f"(r[0]), "f"(r[1]), "f"(r[2]), "f"(r[3]),
           "f"(r[4]), "f"(r[5]), "f"(r[6]), "f"(r[7])
        : "memory");
}

__global__ __launch_bounds__(256, 8) void fwht128_kernel(
    const float* __restrict__ q,
    const float* __restrict__ k,
    const float* __restrict__ v,
    float* __restrict__ out,
    int rowsPerArr)
{
    const int lane = threadIdx.x & 31;
    const int warpGlobal = (int)((blockIdx.x * blockDim.x + threadIdx.x) >> 5);
    const int row = warpGlobal * 4 + (lane >> 3);
    const int j = lane & 7;

    const float* __restrict__ src = (blockIdx.y == 0) ? q : (blockIdx.y == 1) ? k : v;

    const size_t base = (size_t)row * 128 + j * 8;   // float index, 32B-aligned

    float c0[8], c1[8];
    ldg256_cs(src + base,      c0);   // elements 8j+0..7
    ldg256_cs(src + base + 64, c1);   // elements 64+8j+0..7

    // ---- In-chunk stages h=1,2,4 ----
    #define CHUNK_H1(c) { float t; \
        t=c[0]; c[0]=t+c[1]; c[1]=t-c[1]; \
        t=c[2]; c[2]=t+c[3]; c[3]=t-c[3]; \
        t=c[4]; c[4]=t+c[5]; c[5]=t-c[5]; \
        t=c[6]; c[6]=t+c[7]; c[7]=t-c[7]; }
    #define CHUNK_H2(c) { float t; \
        t=c[0]; c[0]=t+c[2]; c[2]=t-c[2]; \
        t=c[1]; c[1]=t+c[3]; c[3]=t-c[3]; \
        t=c[4]; c[4]=t+c[6]; c[6]=t-c[6]; \
        t=c[5]; c[5]=t+c[7]; c[7]=t-c[7]; }
    #define CHUNK_H4(c) { float t; \
        t=c[0]; c[0]=t+c[4]; c[4]=t-c[4]; \
        t=c[1]; c[1]=t+c[5]; c[5]=t-c[5]; \
        t=c[2]; c[2]=t+c[6]; c[6]=t-c[6]; \
        t=c[3]; c[3]=t+c[7]; c[7]=t-c[7]; }
    CHUNK_H1(c0) CHUNK_H1(c1)
    CHUNK_H2(c0) CHUNK_H2(c1)
    CHUNK_H4(c0) CHUNK_H4(c1)

    // ---- Stages h=8,16,32: element bits 3,4,5 live in j -> masks 1,2,4 ----
    // val_new = p + sgn*val  (sgn=+1 low side, -1 high side)
    #pragma unroll
    for (int m = 1; m <= 4; m <<= 1) {
        const float sgn = (j & m) ? -1.0f : 1.0f;
        #pragma unroll
        for (int i = 0; i < 8; i++) {
            float p = __shfl_xor_sync(0xffffffffu, c0[i], m);
            c0[i] = fmaf(c0[i], sgn, p);
        }
        #pragma unroll
        for (int i = 0; i < 8; i++) {
            float p = __shfl_xor_sync(0xffffffffu, c1[i], m);
            c1[i] = fmaf(c1[i], sgn, p);
        }
    }

    // ---- Stage h=64: between the two chunks; fold in final 1/sqrt(128) scale ----
    const float s = 0.08838834764831845f;
    #pragma unroll
    for (int i = 0; i < 8; i++) {
        float t = c0[i];
        c0[i] = (t + c1[i]) * s;
        c1[i] = (t - c1[i]) * s;
    }

    float* __restrict__ dst = out + (size_t)blockIdx.y * rowsPerArr * 128;
    stg256_cs(dst + base,      c0);
    stg256_cs(dst + base + 64, c1);
}

extern "C" void kernel_launch(void* const* d_in, const int* in_sizes, int n_in,
                              void* d_out, int out_size)
{
    const float* q = (const float*)d_in[0];
    const float* k = (const float*)d_in[1];
    const float* v = (const float*)d_in[2];
    float* out = (float*)d_out;

    const int rowsPerArr = in_sizes[0] / 128;   // 524288 (multiple of 32)
    const int rowsPerBlock = (256 / 32) * 4;    // 8 warps * 4 rows = 32
    const int blocksX = rowsPerArr / rowsPerBlock;

    dim3 grid(blocksX, 3, 1);
    fwht128_kernel<<<grid, 256>>>(q, k, v, out, rowsPerArr);
}